// round 1
// baseline (speedup 1.0000x reference)
#include <cuda_runtime.h>
#include <cuda_bf16.h>
#include <math.h>

#define NN 50000
#define EE 800000
#define DD 256
#define HC 256          // H*C = 4*64
#define LL 3
#define SCALE 0.125f    // 1/sqrt(64)

// ---------------- scratch (static device globals; no allocation) -------------
__device__ float g_q[NN * HC];
__device__ float g_k[NN * HC];
__device__ float g_v[NN * HC];
__device__ float g_s[NN * HC];
__device__ float g_hA[NN * HC];
__device__ float g_hB[NN * HC];
__device__ int   g_rowptr[NN + 1];
__device__ int   g_cnt[NN];
__device__ int   g_offs[NN];
__device__ int   g_col[EE];

// ---------------- CSR construction ------------------------------------------
__global__ void zero_counts_kernel() {
    int i = blockIdx.x * blockDim.x + threadIdx.x;
    if (i < NN) { g_cnt[i] = 0; g_offs[i] = 0; }
}

__global__ void count_dst_kernel(const int* __restrict__ edge_index) {
    int e = blockIdx.x * blockDim.x + threadIdx.x;
    if (e < EE) {
        int d = edge_index[EE + e];   // dst row
        atomicAdd(&g_cnt[d], 1);
    }
}

// single-block exclusive scan over g_cnt -> g_rowptr (N=50000, 1024 threads)
__global__ void exscan_kernel() {
    __shared__ int warpsum[32];
    __shared__ int carry_s;
    int tid = threadIdx.x, lane = tid & 31, wid = tid >> 5;
    if (tid == 0) carry_s = 0;
    __syncthreads();
    for (int base = 0; base < NN; base += 1024) {
        int i = base + tid;
        int val = (i < NN) ? g_cnt[i] : 0;
        int x = val;
        #pragma unroll
        for (int off = 1; off < 32; off <<= 1) {
            int y = __shfl_up_sync(0xffffffff, x, off);
            if (lane >= off) x += y;
        }
        if (lane == 31) warpsum[wid] = x;
        __syncthreads();
        if (wid == 0) {
            int w = warpsum[lane];
            #pragma unroll
            for (int off = 1; off < 32; off <<= 1) {
                int y = __shfl_up_sync(0xffffffff, w, off);
                if (lane >= off) w += y;
            }
            warpsum[lane] = w;
        }
        __syncthreads();
        int incl = x + (wid > 0 ? warpsum[wid - 1] : 0);
        int c = carry_s;
        if (i < NN) g_rowptr[i] = c + incl - val;  // exclusive
        __syncthreads();
        if (tid == 1023) carry_s = c + incl;
        __syncthreads();
    }
    if (tid == 0) g_rowptr[NN] = carry_s;
}

__global__ void fill_csr_kernel(const int* __restrict__ edge_index) {
    int e = blockIdx.x * blockDim.x + threadIdx.x;
    if (e < EE) {
        int s = edge_index[e];        // src
        int d = edge_index[EE + e];   // dst
        int pos = g_rowptr[d] + atomicAdd(&g_offs[d], 1);
        g_col[pos] = s;
    }
}

// ---------------- fp32 tiled GEMM with bias: C[M,256] = A[M,256]@B[256,256]+b
#define BM 128
#define BN 128
#define BK 8

__global__ void gemm_bias_kernel(const float* __restrict__ A,
                                 const float* __restrict__ B,
                                 const float* __restrict__ bias,
                                 float* __restrict__ C, int M) {
    __shared__ float As[BK][BM];
    __shared__ float Bs[BK][BN];
    int tid = threadIdx.x;                // 256 threads
    int block_row = blockIdx.y * BM;
    int block_col = blockIdx.x * BN;
    int tx = tid & 15, ty = tid >> 4;     // 16x16 grid, 8x8 microtile

    float acc[8][8];
    #pragma unroll
    for (int i = 0; i < 8; i++)
        #pragma unroll
        for (int j = 0; j < 8; j++) acc[i][j] = 0.f;

    int a_row = tid >> 1;            // 0..127
    int a_k   = (tid & 1) * 4;       // 0 or 4
    int b_k   = tid >> 5;            // 0..7
    int b_col = (tid & 31) * 4;      // 0..124

    for (int k0 = 0; k0 < 256; k0 += BK) {
        int grow = block_row + a_row;
        float4 av = (grow < M) ? *(const float4*)(A + (size_t)grow * 256 + k0 + a_k)
                               : make_float4(0.f, 0.f, 0.f, 0.f);
        As[a_k + 0][a_row] = av.x;
        As[a_k + 1][a_row] = av.y;
        As[a_k + 2][a_row] = av.z;
        As[a_k + 3][a_row] = av.w;
        float4 bv = *(const float4*)(B + (size_t)(k0 + b_k) * 256 + block_col + b_col);
        *(float4*)&Bs[b_k][b_col] = bv;
        __syncthreads();

        #pragma unroll
        for (int kk = 0; kk < BK; kk++) {
            float ar[8], br[8];
            #pragma unroll
            for (int i = 0; i < 8; i++) ar[i] = As[kk][ty * 8 + i];
            #pragma unroll
            for (int j = 0; j < 8; j++) br[j] = Bs[kk][tx * 8 + j];
            #pragma unroll
            for (int i = 0; i < 8; i++)
                #pragma unroll
                for (int j = 0; j < 8; j++) acc[i][j] += ar[i] * br[j];
        }
        __syncthreads();
    }

    #pragma unroll
    for (int i = 0; i < 8; i++) {
        int grow = block_row + ty * 8 + i;
        if (grow < M) {
            #pragma unroll
            for (int j = 0; j < 8; j += 4) {
                int gcol = block_col + tx * 8 + j;
                float4 o;
                o.x = acc[i][j + 0] + bias[gcol + 0];
                o.y = acc[i][j + 1] + bias[gcol + 1];
                o.z = acc[i][j + 2] + bias[gcol + 2];
                o.w = acc[i][j + 3] + bias[gcol + 3];
                *(float4*)(C + (size_t)grow * 256 + gcol) = o;
            }
        }
    }
}

// ---------------- edge attention: one warp per node, online softmax ----------
// lane l owns channels [8l, 8l+8): head = l>>3. Group-reduce over 8 lanes for
// the per-head logit; online max/denominator; fused epilogue relu(agg + s).
__global__ void edge_attn_kernel(const float* __restrict__ q,
                                 const float* __restrict__ k,
                                 const float* __restrict__ v,
                                 const float* __restrict__ s,
                                 float* __restrict__ out) {
    int warp = (blockIdx.x * blockDim.x + threadIdx.x) >> 5;
    if (warp >= NN) return;
    int lane = threadIdx.x & 31;
    const size_t base = (size_t)warp * 256 + lane * 8;

    float4 q0 = *(const float4*)(q + base);
    float4 q1 = *(const float4*)(q + base + 4);

    float m = -1e30f, d = 0.f;
    float acc[8];
    #pragma unroll
    for (int i = 0; i < 8; i++) acc[i] = 0.f;

    int e0 = g_rowptr[warp], e1 = g_rowptr[warp + 1];
    for (int e = e0; e < e1; e++) {
        int src = g_col[e];
        const float* kp = k + (size_t)src * 256 + lane * 8;
        float4 k0 = *(const float4*)kp;
        float4 k1 = *(const float4*)(kp + 4);
        float p = q0.x * k0.x + q0.y * k0.y + q0.z * k0.z + q0.w * k0.w
                + q1.x * k1.x + q1.y * k1.y + q1.z * k1.z + q1.w * k1.w;
        p += __shfl_xor_sync(0xffffffff, p, 1);
        p += __shfl_xor_sync(0xffffffff, p, 2);
        p += __shfl_xor_sync(0xffffffff, p, 4);
        float a = p * SCALE;

        const float* vp = v + (size_t)src * 256 + lane * 8;
        float4 v0 = *(const float4*)vp;
        float4 v1 = *(const float4*)(vp + 4);

        float mn = fmaxf(m, a);
        float r  = __expf(m - mn);
        float pe = __expf(a - mn);
        d = d * r + pe;
        acc[0] = acc[0] * r + pe * v0.x;
        acc[1] = acc[1] * r + pe * v0.y;
        acc[2] = acc[2] * r + pe * v0.z;
        acc[3] = acc[3] * r + pe * v0.w;
        acc[4] = acc[4] * r + pe * v1.x;
        acc[5] = acc[5] * r + pe * v1.y;
        acc[6] = acc[6] * r + pe * v1.z;
        acc[7] = acc[7] * r + pe * v1.w;
        m = mn;
    }

    float inv = (d > 0.f) ? 1.f / d : 0.f;
    const float* sp = s + base;
    float4 s0 = *(const float4*)sp;
    float4 s1 = *(const float4*)(sp + 4);
    float4 o0, o1;
    o0.x = fmaxf(acc[0] * inv + s0.x, 0.f);
    o0.y = fmaxf(acc[1] * inv + s0.y, 0.f);
    o0.z = fmaxf(acc[2] * inv + s0.z, 0.f);
    o0.w = fmaxf(acc[3] * inv + s0.w, 0.f);
    o1.x = fmaxf(acc[4] * inv + s1.x, 0.f);
    o1.y = fmaxf(acc[5] * inv + s1.y, 0.f);
    o1.z = fmaxf(acc[6] * inv + s1.z, 0.f);
    o1.w = fmaxf(acc[7] * inv + s1.w, 0.f);
    *(float4*)(out + base)     = o0;
    *(float4*)(out + base + 4) = o1;
}

// ---------------- launch ------------------------------------------------------
extern "C" void kernel_launch(void* const* d_in, const int* in_sizes, int n_in,
                              void* d_out, int out_size) {
    const float* x   = (const float*)d_in[0];
    const int*   ei  = (const int*)d_in[1];
    const float* Wq  = (const float*)d_in[2];
    const float* bq  = (const float*)d_in[3];
    const float* Wk  = (const float*)d_in[4];
    const float* bk  = (const float*)d_in[5];
    const float* Wv  = (const float*)d_in[6];
    const float* bv  = (const float*)d_in[7];
    const float* Ws  = (const float*)d_in[8];
    const float* bs  = (const float*)d_in[9];
    float* out = (float*)d_out;

    float *q, *k, *v, *s, *hA, *hB;
    cudaGetSymbolAddress((void**)&q,  g_q);
    cudaGetSymbolAddress((void**)&k,  g_k);
    cudaGetSymbolAddress((void**)&v,  g_v);
    cudaGetSymbolAddress((void**)&s,  g_s);
    cudaGetSymbolAddress((void**)&hA, g_hA);
    cudaGetSymbolAddress((void**)&hB, g_hB);

    // --- build CSR (dst -> list of src) once per launch ---
    zero_counts_kernel<<<(NN + 255) / 256, 256>>>();
    count_dst_kernel<<<(EE + 255) / 256, 256>>>(ei);
    exscan_kernel<<<1, 1024>>>();
    fill_csr_kernel<<<(EE + 255) / 256, 256>>>(ei);

    dim3 gemm_grid(2, (NN + BM - 1) / BM);   // 2 col tiles x 391 row tiles
    int edge_blocks = (NN + 7) / 8;          // 8 warps per block

    const float* hin = x;
    for (int l = 0; l < LL; l++) {
        const float* wq = Wq + (size_t)l * DD * HC;
        const float* wk = Wk + (size_t)l * DD * HC;
        const float* wv = Wv + (size_t)l * DD * HC;
        const float* ws = Ws + (size_t)l * DD * HC;
        gemm_bias_kernel<<<gemm_grid, 256>>>(hin, wq, bq + l * HC, q, NN);
        gemm_bias_kernel<<<gemm_grid, 256>>>(hin, wk, bk + l * HC, k, NN);
        gemm_bias_kernel<<<gemm_grid, 256>>>(hin, wv, bv + l * HC, v, NN);
        gemm_bias_kernel<<<gemm_grid, 256>>>(hin, ws, bs + l * HC, s, NN);

        float* hout = (l == LL - 1) ? out : ((l == 0) ? hA : hB);
        edge_attn_kernel<<<edge_blocks, 256>>>(q, k, v, s, hout);
        hin = hout;
    }
}

// round 2
// speedup vs baseline: 1.7391x; 1.7391x over previous
#include <cuda_runtime.h>
#include <cuda_bf16.h>
#include <math.h>
#include <stdint.h>

#define NN 50000
#define EE 800000
#define DD 256
#define HC 256          // H*C = 4*64
#define LL 3
#define SCALE 0.125f    // 1/sqrt(64)

// ---------------- scratch (static device globals; no allocation) -------------
__device__ float g_q[NN * HC];
__device__ float g_k[NN * HC];
__device__ float g_v[NN * HC];
__device__ float g_s[NN * HC];
__device__ float g_hA[NN * HC];
__device__ float g_hB[NN * HC];
__device__ int   g_rowptr[NN + 1];
__device__ int   g_cnt[NN];
__device__ int   g_offs[NN];
__device__ int   g_col[EE];

// ---------------- CSR construction ------------------------------------------
__global__ void zero_counts_kernel() {
    int i = blockIdx.x * blockDim.x + threadIdx.x;
    if (i < NN) { g_cnt[i] = 0; g_offs[i] = 0; }
}

__global__ void count_dst_kernel(const int* __restrict__ edge_index) {
    int e = blockIdx.x * blockDim.x + threadIdx.x;
    if (e < EE) {
        int d = edge_index[EE + e];   // dst row
        atomicAdd(&g_cnt[d], 1);
    }
}

// single-block exclusive scan over g_cnt -> g_rowptr
__global__ void exscan_kernel() {
    __shared__ int warpsum[32];
    __shared__ int carry_s;
    int tid = threadIdx.x, lane = tid & 31, wid = tid >> 5;
    if (tid == 0) carry_s = 0;
    __syncthreads();
    for (int base = 0; base < NN; base += 1024) {
        int i = base + tid;
        int val = (i < NN) ? g_cnt[i] : 0;
        int x = val;
        #pragma unroll
        for (int off = 1; off < 32; off <<= 1) {
            int y = __shfl_up_sync(0xffffffff, x, off);
            if (lane >= off) x += y;
        }
        if (lane == 31) warpsum[wid] = x;
        __syncthreads();
        if (wid == 0) {
            int w = warpsum[lane];
            #pragma unroll
            for (int off = 1; off < 32; off <<= 1) {
                int y = __shfl_up_sync(0xffffffff, w, off);
                if (lane >= off) w += y;
            }
            warpsum[lane] = w;
        }
        __syncthreads();
        int incl = x + (wid > 0 ? warpsum[wid - 1] : 0);
        int c = carry_s;
        if (i < NN) g_rowptr[i] = c + incl - val;  // exclusive
        __syncthreads();
        if (tid == 1023) carry_s = c + incl;
        __syncthreads();
    }
    if (tid == 0) g_rowptr[NN] = carry_s;
}

__global__ void fill_csr_kernel(const int* __restrict__ edge_index) {
    int e = blockIdx.x * blockDim.x + threadIdx.x;
    if (e < EE) {
        int s = edge_index[e];        // src
        int d = edge_index[EE + e];   // dst
        int pos = g_rowptr[d] + atomicAdd(&g_offs[d], 1);
        g_col[pos] = s;
    }
}

// ---------------- TF32 tensor-core GEMM: C[M,256] = A[M,256]@B[256,256]+bias
// 128x128 block tile, BK=16, 8 warps (warp tile 32x64), mma.m16n8k8.tf32.
#define BM 128
#define BN 128
#define BK 16
#define ASTRIDE 20      // banks (20*m+k)%32 distinct for frag pattern
#define BSTRIDE 136     // banks (8*k+n)%32 distinct for frag pattern

__device__ __forceinline__ uint32_t f2tf32(float f) {
    uint32_t r;
    asm("cvt.rna.tf32.f32 %0, %1;" : "=r"(r) : "f"(f));
    return r;
}

__global__ __launch_bounds__(256, 1)
void gemm_tf32_kernel(const float* __restrict__ A,
                      const float* __restrict__ B,
                      const float* __restrict__ bias,
                      float* __restrict__ C, int M) {
    __shared__ uint32_t sA[2][BM * ASTRIDE];   // [m][k] stride 20
    __shared__ uint32_t sB[2][BK * BSTRIDE];   // [k][n] stride 136

    const int tid  = threadIdx.x;
    const int lane = tid & 31;
    const int wid  = tid >> 5;
    const int wm   = (wid & 3) * 32;   // warp m offset
    const int wn   = (wid >> 2) * 64;  // warp n offset
    const int brow = blockIdx.y * BM;
    const int bcol = blockIdx.x * BN;

    float c[2][8][4];
    #pragma unroll
    for (int i = 0; i < 2; i++)
        #pragma unroll
        for (int j = 0; j < 8; j++)
            #pragma unroll
            for (int r = 0; r < 4; r++) c[i][j][r] = 0.f;

    // global load mapping (per thread: 2 float4 of A, 2 float4 of B)
    // A: idx = tid + i*256 -> arow = idx>>2 (0..127), akf = (idx&3)*4
    // B: idx = tid + i*256 -> bkr  = idx>>5 (0..15),  bnf = (idx&31)*4
    int arow[2], akf[2], bkr[2], bnf[2];
    const float* aptr[2];
    const float* bptr0[2];
    #pragma unroll
    for (int i = 0; i < 2; i++) {
        int idx = tid + i * 256;
        arow[i] = idx >> 2;  akf[i] = (idx & 3) * 4;
        bkr[i]  = idx >> 5;  bnf[i] = (idx & 31) * 4;
        int gr = brow + arow[i];
        if (gr >= M) gr = M - 1;               // clamp; stores guarded later
        aptr[i]  = A + (size_t)gr * 256 + akf[i];
        bptr0[i] = B + (size_t)bkr[i] * 256 + bcol + bnf[i];
    }

    // preload tile 0 into buffer 0
    #pragma unroll
    for (int i = 0; i < 2; i++) {
        float4 av = *(const float4*)(aptr[i]);
        uint32_t* d = &sA[0][arow[i] * ASTRIDE + akf[i]];
        d[0] = f2tf32(av.x); d[1] = f2tf32(av.y);
        d[2] = f2tf32(av.z); d[3] = f2tf32(av.w);
        float4 bv = *(const float4*)(bptr0[i]);
        uint32_t* e = &sB[0][bkr[i] * BSTRIDE + bnf[i]];
        e[0] = f2tf32(bv.x); e[1] = f2tf32(bv.y);
        e[2] = f2tf32(bv.z); e[3] = f2tf32(bv.w);
    }
    __syncthreads();

    const int NSTEP = 256 / BK;   // 16
    float4 pa[2], pb[2];

    for (int t = 0; t < NSTEP; t++) {
        const int cur = t & 1;
        const bool has_next = (t + 1 < NSTEP);
        if (has_next) {
            int k0 = (t + 1) * BK;
            #pragma unroll
            for (int i = 0; i < 2; i++) {
                pa[i] = *(const float4*)(aptr[i] + k0);
                pb[i] = *(const float4*)(bptr0[i] + (size_t)k0 * 256);
            }
        }

        const uint32_t* __restrict__ sa = sA[cur];
        const uint32_t* __restrict__ sb = sB[cur];
        const int l4 = lane & 3, l8 = lane >> 2;

        #pragma unroll
        for (int kb = 0; kb < BK; kb += 8) {
            uint32_t af[2][4];
            #pragma unroll
            for (int mt = 0; mt < 2; mt++) {
                int mrow = wm + mt * 16 + l8;
                const uint32_t* p = &sa[mrow * ASTRIDE + kb + l4];
                af[mt][0] = p[0];
                af[mt][1] = p[8 * ASTRIDE];
                af[mt][2] = p[4];
                af[mt][3] = p[8 * ASTRIDE + 4];
            }
            uint32_t bf[8][2];
            #pragma unroll
            for (int nt = 0; nt < 8; nt++) {
                const uint32_t* p = &sb[(kb + l4) * BSTRIDE + wn + nt * 8 + l8];
                bf[nt][0] = p[0];
                bf[nt][1] = p[4 * BSTRIDE];
            }
            #pragma unroll
            for (int mt = 0; mt < 2; mt++)
                #pragma unroll
                for (int nt = 0; nt < 8; nt++) {
                    asm volatile(
                        "mma.sync.aligned.m16n8k8.row.col.f32.tf32.tf32.f32 "
                        "{%0,%1,%2,%3}, {%4,%5,%6,%7}, {%8,%9}, {%0,%1,%2,%3};"
                        : "+f"(c[mt][nt][0]), "+f"(c[mt][nt][1]),
                          "+f"(c[mt][nt][2]), "+f"(c[mt][nt][3])
                        : "r"(af[mt][0]), "r"(af[mt][1]),
                          "r"(af[mt][2]), "r"(af[mt][3]),
                          "r"(bf[nt][0]), "r"(bf[nt][1]));
                }
        }

        if (has_next) {
            const int nxt = cur ^ 1;
            #pragma unroll
            for (int i = 0; i < 2; i++) {
                uint32_t* d = &sA[nxt][arow[i] * ASTRIDE + akf[i]];
                d[0] = f2tf32(pa[i].x); d[1] = f2tf32(pa[i].y);
                d[2] = f2tf32(pa[i].z); d[3] = f2tf32(pa[i].w);
                uint32_t* e = &sB[nxt][bkr[i] * BSTRIDE + bnf[i]];
                e[0] = f2tf32(pb[i].x); e[1] = f2tf32(pb[i].y);
                e[2] = f2tf32(pb[i].z); e[3] = f2tf32(pb[i].w);
            }
        }
        __syncthreads();
    }

    // epilogue: C = acc + bias
    const int l4 = lane & 3, l8 = lane >> 2;
    #pragma unroll
    for (int mt = 0; mt < 2; mt++) {
        #pragma unroll
        for (int half = 0; half < 2; half++) {
            int grow = brow + wm + mt * 16 + l8 + half * 8;
            if (grow < M) {
                #pragma unroll
                for (int nt = 0; nt < 8; nt++) {
                    int gcol = bcol + wn + nt * 8 + 2 * l4;
                    float2 o;
                    o.x = c[mt][nt][half * 2 + 0] + bias[gcol + 0];
                    o.y = c[mt][nt][half * 2 + 1] + bias[gcol + 1];
                    *(float2*)(C + (size_t)grow * 256 + gcol) = o;
                }
            }
        }
    }
}

// ---------------- edge attention: one warp per node, online softmax ----------
__global__ void edge_attn_kernel(const float* __restrict__ q,
                                 const float* __restrict__ k,
                                 const float* __restrict__ v,
                                 const float* __restrict__ s,
                                 float* __restrict__ out) {
    int warp = (blockIdx.x * blockDim.x + threadIdx.x) >> 5;
    if (warp >= NN) return;
    int lane = threadIdx.x & 31;
    const size_t base = (size_t)warp * 256 + lane * 8;

    float4 q0 = *(const float4*)(q + base);
    float4 q1 = *(const float4*)(q + base + 4);

    float m = -1e30f, d = 0.f;
    float acc[8];
    #pragma unroll
    for (int i = 0; i < 8; i++) acc[i] = 0.f;

    int e0 = g_rowptr[warp], e1 = g_rowptr[warp + 1];
    for (int e = e0; e < e1; e++) {
        int src = g_col[e];
        const float* kp = k + (size_t)src * 256 + lane * 8;
        float4 k0 = *(const float4*)kp;
        float4 k1 = *(const float4*)(kp + 4);
        float p = q0.x * k0.x + q0.y * k0.y + q0.z * k0.z + q0.w * k0.w
                + q1.x * k1.x + q1.y * k1.y + q1.z * k1.z + q1.w * k1.w;
        p += __shfl_xor_sync(0xffffffff, p, 1);
        p += __shfl_xor_sync(0xffffffff, p, 2);
        p += __shfl_xor_sync(0xffffffff, p, 4);
        float a = p * SCALE;

        const float* vp = v + (size_t)src * 256 + lane * 8;
        float4 v0 = *(const float4*)vp;
        float4 v1 = *(const float4*)(vp + 4);

        float mn = fmaxf(m, a);
        float r  = __expf(m - mn);
        float pe = __expf(a - mn);
        d = d * r + pe;
        acc[0] = acc[0] * r + pe * v0.x;
        acc[1] = acc[1] * r + pe * v0.y;
        acc[2] = acc[2] * r + pe * v0.z;
        acc[3] = acc[3] * r + pe * v0.w;
        acc[4] = acc[4] * r + pe * v1.x;
        acc[5] = acc[5] * r + pe * v1.y;
        acc[6] = acc[6] * r + pe * v1.z;
        acc[7] = acc[7] * r + pe * v1.w;
        m = mn;
    }

    float inv = (d > 0.f) ? 1.f / d : 0.f;
    const float* sp = s + base;
    float4 s0 = *(const float4*)sp;
    float4 s1 = *(const float4*)(sp + 4);
    float4 o0, o1;
    o0.x = fmaxf(acc[0] * inv + s0.x, 0.f);
    o0.y = fmaxf(acc[1] * inv + s0.y, 0.f);
    o0.z = fmaxf(acc[2] * inv + s0.z, 0.f);
    o0.w = fmaxf(acc[3] * inv + s0.w, 0.f);
    o1.x = fmaxf(acc[4] * inv + s1.x, 0.f);
    o1.y = fmaxf(acc[5] * inv + s1.y, 0.f);
    o1.z = fmaxf(acc[6] * inv + s1.z, 0.f);
    o1.w = fmaxf(acc[7] * inv + s1.w, 0.f);
    *(float4*)(out + base)     = o0;
    *(float4*)(out + base + 4) = o1;
}

// ---------------- launch ------------------------------------------------------
extern "C" void kernel_launch(void* const* d_in, const int* in_sizes, int n_in,
                              void* d_out, int out_size) {
    const float* x   = (const float*)d_in[0];
    const int*   ei  = (const int*)d_in[1];
    const float* Wq  = (const float*)d_in[2];
    const float* bq  = (const float*)d_in[3];
    const float* Wk  = (const float*)d_in[4];
    const float* bk  = (const float*)d_in[5];
    const float* Wv  = (const float*)d_in[6];
    const float* bv  = (const float*)d_in[7];
    const float* Ws  = (const float*)d_in[8];
    const float* bs  = (const float*)d_in[9];
    float* out = (float*)d_out;

    float *q, *k, *v, *s, *hA, *hB;
    cudaGetSymbolAddress((void**)&q,  g_q);
    cudaGetSymbolAddress((void**)&k,  g_k);
    cudaGetSymbolAddress((void**)&v,  g_v);
    cudaGetSymbolAddress((void**)&s,  g_s);
    cudaGetSymbolAddress((void**)&hA, g_hA);
    cudaGetSymbolAddress((void**)&hB, g_hB);

    // --- build CSR (dst -> list of src) once per launch ---
    zero_counts_kernel<<<(NN + 255) / 256, 256>>>();
    count_dst_kernel<<<(EE + 255) / 256, 256>>>(ei);
    exscan_kernel<<<1, 1024>>>();
    fill_csr_kernel<<<(EE + 255) / 256, 256>>>(ei);

    dim3 gemm_grid(2, (NN + BM - 1) / BM);   // 2 col tiles x 391 row tiles
    int edge_blocks = (NN + 7) / 8;          // 8 warps per block

    const float* hin = x;
    for (int l = 0; l < LL; l++) {
        const float* wq = Wq + (size_t)l * DD * HC;
        const float* wk = Wk + (size_t)l * DD * HC;
        const float* wv = Wv + (size_t)l * DD * HC;
        const float* ws = Ws + (size_t)l * DD * HC;
        gemm_tf32_kernel<<<gemm_grid, 256>>>(hin, wq, bq + l * HC, q, NN);
        gemm_tf32_kernel<<<gemm_grid, 256>>>(hin, wk, bk + l * HC, k, NN);
        gemm_tf32_kernel<<<gemm_grid, 256>>>(hin, wv, bv + l * HC, v, NN);
        gemm_tf32_kernel<<<gemm_grid, 256>>>(hin, ws, bs + l * HC, s, NN);

        float* hout = (l == LL - 1) ? out : ((l == 0) ? hA : hB);
        edge_attn_kernel<<<edge_blocks, 256>>>(q, k, v, s, hout);
        hin = hout;
    }
}

// round 3
// speedup vs baseline: 2.4098x; 1.3857x over previous
#include <cuda_runtime.h>
#include <cuda_bf16.h>
#include <math.h>
#include <stdint.h>

#define NN 50000
#define EE 800000
#define DD 256
#define HC 256          // H*C = 4*64
#define LL 3
#define SCALE 0.125f    // 1/sqrt(64)

// ---------------- scratch (static device globals; no allocation) -------------
__device__ float g_qkvs[NN * 1024];   // per node: [q(256) | k(256) | v(256) | s(256)]
__device__ float g_hA[NN * HC];
__device__ float g_hB[NN * HC];
__device__ int   g_rowptr[NN + 1];
__device__ int   g_cnt[NN];
__device__ int   g_offs[NN];
__device__ int   g_col[EE];

// ---------------- CSR construction ------------------------------------------
__global__ void zero_counts_kernel() {
    int i = blockIdx.x * blockDim.x + threadIdx.x;
    if (i < NN) { g_cnt[i] = 0; g_offs[i] = 0; }
}

__global__ void count_dst_kernel(const int* __restrict__ edge_index) {
    int e = blockIdx.x * blockDim.x + threadIdx.x;
    if (e < EE) {
        int d = edge_index[EE + e];   // dst row
        atomicAdd(&g_cnt[d], 1);
    }
}

// single-block exclusive scan over g_cnt -> g_rowptr
__global__ void exscan_kernel() {
    __shared__ int warpsum[32];
    __shared__ int carry_s;
    int tid = threadIdx.x, lane = tid & 31, wid = tid >> 5;
    if (tid == 0) carry_s = 0;
    __syncthreads();
    for (int base = 0; base < NN; base += 1024) {
        int i = base + tid;
        int val = (i < NN) ? g_cnt[i] : 0;
        int x = val;
        #pragma unroll
        for (int off = 1; off < 32; off <<= 1) {
            int y = __shfl_up_sync(0xffffffff, x, off);
            if (lane >= off) x += y;
        }
        if (lane == 31) warpsum[wid] = x;
        __syncthreads();
        if (wid == 0) {
            int w = warpsum[lane];
            #pragma unroll
            for (int off = 1; off < 32; off <<= 1) {
                int y = __shfl_up_sync(0xffffffff, w, off);
                if (lane >= off) w += y;
            }
            warpsum[lane] = w;
        }
        __syncthreads();
        int incl = x + (wid > 0 ? warpsum[wid - 1] : 0);
        int c = carry_s;
        if (i < NN) g_rowptr[i] = c + incl - val;  // exclusive
        __syncthreads();
        if (tid == 1023) carry_s = c + incl;
        __syncthreads();
    }
    if (tid == 0) g_rowptr[NN] = carry_s;
}

__global__ void fill_csr_kernel(const int* __restrict__ edge_index) {
    int e = blockIdx.x * blockDim.x + threadIdx.x;
    if (e < EE) {
        int s = edge_index[e];        // src
        int d = edge_index[EE + e];   // dst
        int pos = g_rowptr[d] + atomicAdd(&g_offs[d], 1);
        g_col[pos] = s;
    }
}

// ---------------- fused TF32 GEMM: [q|k|v|s] = A@{Wq,Wk,Wv,Ws} + bias --------
// grid.x = 8 (4 matrices x 2 col tiles), grid.y = row tiles.
// 128x128 block tile, BK=16, 8 warps (warp tile 32x64), mma.m16n8k8.tf32.
#define BM 128
#define BN 128
#define BK 16
#define ASTRIDE 20      // banks (20*m+k)%32 distinct for frag pattern
#define BSTRIDE 136     // banks (8*k+n)%32 distinct for frag pattern

__device__ __forceinline__ uint32_t f2tf32(float f) {
    uint32_t r;
    asm("cvt.rna.tf32.f32 %0, %1;" : "=r"(r) : "f"(f));
    return r;
}

__global__ __launch_bounds__(256, 2)
void gemm_qkvs_kernel(const float* __restrict__ A,
                      const float* __restrict__ W0, const float* __restrict__ W1,
                      const float* __restrict__ W2, const float* __restrict__ W3,
                      const float* __restrict__ b0, const float* __restrict__ b1,
                      const float* __restrict__ b2, const float* __restrict__ b3,
                      float* __restrict__ C, int M) {
    __shared__ uint32_t sA[2][BM * ASTRIDE];   // [m][k] stride 20
    __shared__ uint32_t sB[2][BK * BSTRIDE];   // [k][n] stride 136

    const int which = blockIdx.x >> 1;
    const float* B    = (which == 0) ? W0 : (which == 1) ? W1 : (which == 2) ? W2 : W3;
    const float* bias = (which == 0) ? b0 : (which == 1) ? b1 : (which == 2) ? b2 : b3;

    const int tid  = threadIdx.x;
    const int lane = tid & 31;
    const int wid  = tid >> 5;
    const int wm   = (wid & 3) * 32;   // warp m offset
    const int wn   = (wid >> 2) * 64;  // warp n offset
    const int brow = blockIdx.y * BM;
    const int bcol = (blockIdx.x & 1) * BN;   // col within the 256-wide matrix

    float c[2][8][4];
    #pragma unroll
    for (int i = 0; i < 2; i++)
        #pragma unroll
        for (int j = 0; j < 8; j++)
            #pragma unroll
            for (int r = 0; r < 4; r++) c[i][j][r] = 0.f;

    int arow[2], akf[2], bkr[2], bnf[2];
    const float* aptr[2];
    const float* bptr0[2];
    #pragma unroll
    for (int i = 0; i < 2; i++) {
        int idx = tid + i * 256;
        arow[i] = idx >> 2;  akf[i] = (idx & 3) * 4;
        bkr[i]  = idx >> 5;  bnf[i] = (idx & 31) * 4;
        int gr = brow + arow[i];
        if (gr >= M) gr = M - 1;               // clamp; stores guarded later
        aptr[i]  = A + (size_t)gr * 256 + akf[i];
        bptr0[i] = B + (size_t)bkr[i] * 256 + bcol + bnf[i];
    }

    // preload tile 0 into buffer 0
    #pragma unroll
    for (int i = 0; i < 2; i++) {
        float4 av = *(const float4*)(aptr[i]);
        uint32_t* d = &sA[0][arow[i] * ASTRIDE + akf[i]];
        d[0] = f2tf32(av.x); d[1] = f2tf32(av.y);
        d[2] = f2tf32(av.z); d[3] = f2tf32(av.w);
        float4 bv = *(const float4*)(bptr0[i]);
        uint32_t* e = &sB[0][bkr[i] * BSTRIDE + bnf[i]];
        e[0] = f2tf32(bv.x); e[1] = f2tf32(bv.y);
        e[2] = f2tf32(bv.z); e[3] = f2tf32(bv.w);
    }
    __syncthreads();

    const int NSTEP = 256 / BK;   // 16
    float4 pa[2], pb[2];

    for (int t = 0; t < NSTEP; t++) {
        const int cur = t & 1;
        const bool has_next = (t + 1 < NSTEP);
        if (has_next) {
            int k0 = (t + 1) * BK;
            #pragma unroll
            for (int i = 0; i < 2; i++) {
                pa[i] = *(const float4*)(aptr[i] + k0);
                pb[i] = *(const float4*)(bptr0[i] + (size_t)k0 * 256);
            }
        }

        const uint32_t* __restrict__ sa = sA[cur];
        const uint32_t* __restrict__ sb = sB[cur];
        const int l4 = lane & 3, l8 = lane >> 2;

        #pragma unroll
        for (int kb = 0; kb < BK; kb += 8) {
            uint32_t af[2][4];
            #pragma unroll
            for (int mt = 0; mt < 2; mt++) {
                int mrow = wm + mt * 16 + l8;
                const uint32_t* p = &sa[mrow * ASTRIDE + kb + l4];
                af[mt][0] = p[0];
                af[mt][1] = p[8 * ASTRIDE];
                af[mt][2] = p[4];
                af[mt][3] = p[8 * ASTRIDE + 4];
            }
            uint32_t bf[8][2];
            #pragma unroll
            for (int nt = 0; nt < 8; nt++) {
                const uint32_t* p = &sb[(kb + l4) * BSTRIDE + wn + nt * 8 + l8];
                bf[nt][0] = p[0];
                bf[nt][1] = p[4 * BSTRIDE];
            }
            #pragma unroll
            for (int mt = 0; mt < 2; mt++)
                #pragma unroll
                for (int nt = 0; nt < 8; nt++) {
                    asm volatile(
                        "mma.sync.aligned.m16n8k8.row.col.f32.tf32.tf32.f32 "
                        "{%0,%1,%2,%3}, {%4,%5,%6,%7}, {%8,%9}, {%0,%1,%2,%3};"
                        : "+f"(c[mt][nt][0]), "+f"(c[mt][nt][1]),
                          "+f"(c[mt][nt][2]), "+f"(c[mt][nt][3])
                        : "r"(af[mt][0]), "r"(af[mt][1]),
                          "r"(af[mt][2]), "r"(af[mt][3]),
                          "r"(bf[nt][0]), "r"(bf[nt][1]));
                }
        }

        if (has_next) {
            const int nxt = cur ^ 1;
            #pragma unroll
            for (int i = 0; i < 2; i++) {
                uint32_t* d = &sA[nxt][arow[i] * ASTRIDE + akf[i]];
                d[0] = f2tf32(pa[i].x); d[1] = f2tf32(pa[i].y);
                d[2] = f2tf32(pa[i].z); d[3] = f2tf32(pa[i].w);
                uint32_t* e = &sB[nxt][bkr[i] * BSTRIDE + bnf[i]];
                e[0] = f2tf32(pb[i].x); e[1] = f2tf32(pb[i].y);
                e[2] = f2tf32(pb[i].z); e[3] = f2tf32(pb[i].w);
            }
        }
        __syncthreads();
    }

    // epilogue: C[row*1024 + which*256 + col] = acc + bias
    const int l4 = lane & 3, l8 = lane >> 2;
    float* Cb = C + (size_t)which * 256;
    #pragma unroll
    for (int mt = 0; mt < 2; mt++) {
        #pragma unroll
        for (int half = 0; half < 2; half++) {
            int grow = brow + wm + mt * 16 + l8 + half * 8;
            if (grow < M) {
                #pragma unroll
                for (int nt = 0; nt < 8; nt++) {
                    int gcol = bcol + wn + nt * 8 + 2 * l4;
                    float2 o;
                    o.x = c[mt][nt][half * 2 + 0] + bias[gcol + 0];
                    o.y = c[mt][nt][half * 2 + 1] + bias[gcol + 1];
                    *(float2*)(Cb + (size_t)grow * 1024 + gcol) = o;
                }
            }
        }
    }
}

// ---------------- edge attention: one warp per node, online softmax ----------
// qkvs layout: node*1024 + {0:q, 256:k, 512:v, 768:s} + channel.
// 2-edge unroll: independent logit chains, merged rescale -> MLP 4.
__global__ void edge_attn_kernel(const float* __restrict__ qkvs,
                                 float* __restrict__ out) {
    int warp = (blockIdx.x * blockDim.x + threadIdx.x) >> 5;
    if (warp >= NN) return;
    int lane = threadIdx.x & 31;
    const int ch = lane * 8;
    const float* nb = qkvs + (size_t)warp * 1024;

    float4 q0 = *(const float4*)(nb + ch);
    float4 q1 = *(const float4*)(nb + ch + 4);

    float m = -1e30f, d = 0.f;
    float acc[8];
    #pragma unroll
    for (int i = 0; i < 8; i++) acc[i] = 0.f;

    const int e0 = g_rowptr[warp], e1 = g_rowptr[warp + 1];
    int e = e0;

    for (; e + 1 < e1; e += 2) {
        int s0 = g_col[e], s1 = g_col[e + 1];
        const float* k0p = qkvs + (size_t)s0 * 1024 + 256 + ch;
        const float* k1p = qkvs + (size_t)s1 * 1024 + 256 + ch;
        float4 ka0 = *(const float4*)k0p;
        float4 ka1 = *(const float4*)(k0p + 4);
        float4 kb0 = *(const float4*)k1p;
        float4 kb1 = *(const float4*)(k1p + 4);
        const float* v0p = qkvs + (size_t)s0 * 1024 + 512 + ch;
        const float* v1p = qkvs + (size_t)s1 * 1024 + 512 + ch;
        float4 va0 = *(const float4*)v0p;
        float4 va1 = *(const float4*)(v0p + 4);
        float4 vb0 = *(const float4*)v1p;
        float4 vb1 = *(const float4*)(v1p + 4);

        float p0 = q0.x * ka0.x + q0.y * ka0.y + q0.z * ka0.z + q0.w * ka0.w
                 + q1.x * ka1.x + q1.y * ka1.y + q1.z * ka1.z + q1.w * ka1.w;
        float p1 = q0.x * kb0.x + q0.y * kb0.y + q0.z * kb0.z + q0.w * kb0.w
                 + q1.x * kb1.x + q1.y * kb1.y + q1.z * kb1.z + q1.w * kb1.w;
        p0 += __shfl_xor_sync(0xffffffff, p0, 1);
        p1 += __shfl_xor_sync(0xffffffff, p1, 1);
        p0 += __shfl_xor_sync(0xffffffff, p0, 2);
        p1 += __shfl_xor_sync(0xffffffff, p1, 2);
        p0 += __shfl_xor_sync(0xffffffff, p0, 4);
        p1 += __shfl_xor_sync(0xffffffff, p1, 4);
        float a0 = p0 * SCALE, a1 = p1 * SCALE;

        float mn = fmaxf(m, fmaxf(a0, a1));
        float r   = __expf(m - mn);
        float pe0 = __expf(a0 - mn);
        float pe1 = __expf(a1 - mn);
        d = d * r + pe0 + pe1;
        acc[0] = acc[0] * r + pe0 * va0.x + pe1 * vb0.x;
        acc[1] = acc[1] * r + pe0 * va0.y + pe1 * vb0.y;
        acc[2] = acc[2] * r + pe0 * va0.z + pe1 * vb0.z;
        acc[3] = acc[3] * r + pe0 * va0.w + pe1 * vb0.w;
        acc[4] = acc[4] * r + pe0 * va1.x + pe1 * vb1.x;
        acc[5] = acc[5] * r + pe0 * va1.y + pe1 * vb1.y;
        acc[6] = acc[6] * r + pe0 * va1.z + pe1 * vb1.z;
        acc[7] = acc[7] * r + pe0 * va1.w + pe1 * vb1.w;
        m = mn;
    }

    if (e < e1) {   // odd tail
        int s0 = g_col[e];
        const float* kp = qkvs + (size_t)s0 * 1024 + 256 + ch;
        float4 ka0 = *(const float4*)kp;
        float4 ka1 = *(const float4*)(kp + 4);
        const float* vp = qkvs + (size_t)s0 * 1024 + 512 + ch;
        float4 va0 = *(const float4*)vp;
        float4 va1 = *(const float4*)(vp + 4);
        float p = q0.x * ka0.x + q0.y * ka0.y + q0.z * ka0.z + q0.w * ka0.w
                + q1.x * ka1.x + q1.y * ka1.y + q1.z * ka1.z + q1.w * ka1.w;
        p += __shfl_xor_sync(0xffffffff, p, 1);
        p += __shfl_xor_sync(0xffffffff, p, 2);
        p += __shfl_xor_sync(0xffffffff, p, 4);
        float a = p * SCALE;
        float mn = fmaxf(m, a);
        float r  = __expf(m - mn);
        float pe = __expf(a - mn);
        d = d * r + pe;
        acc[0] = acc[0] * r + pe * va0.x;
        acc[1] = acc[1] * r + pe * va0.y;
        acc[2] = acc[2] * r + pe * va0.z;
        acc[3] = acc[3] * r + pe * va0.w;
        acc[4] = acc[4] * r + pe * va1.x;
        acc[5] = acc[5] * r + pe * va1.y;
        acc[6] = acc[6] * r + pe * va1.z;
        acc[7] = acc[7] * r + pe * va1.w;
    }

    float inv = (d > 0.f) ? 1.f / d : 0.f;
    const float* sp = nb + 768 + ch;
    float4 s0v = *(const float4*)sp;
    float4 s1v = *(const float4*)(sp + 4);
    float4 o0, o1;
    o0.x = fmaxf(acc[0] * inv + s0v.x, 0.f);
    o0.y = fmaxf(acc[1] * inv + s0v.y, 0.f);
    o0.z = fmaxf(acc[2] * inv + s0v.z, 0.f);
    o0.w = fmaxf(acc[3] * inv + s0v.w, 0.f);
    o1.x = fmaxf(acc[4] * inv + s1v.x, 0.f);
    o1.y = fmaxf(acc[5] * inv + s1v.y, 0.f);
    o1.z = fmaxf(acc[6] * inv + s1v.z, 0.f);
    o1.w = fmaxf(acc[7] * inv + s1v.w, 0.f);
    float* op = out + (size_t)warp * 256 + ch;
    *(float4*)op       = o0;
    *(float4*)(op + 4) = o1;
}

// ---------------- launch ------------------------------------------------------
extern "C" void kernel_launch(void* const* d_in, const int* in_sizes, int n_in,
                              void* d_out, int out_size) {
    const float* x   = (const float*)d_in[0];
    const int*   ei  = (const int*)d_in[1];
    const float* Wq  = (const float*)d_in[2];
    const float* bq  = (const float*)d_in[3];
    const float* Wk  = (const float*)d_in[4];
    const float* bk  = (const float*)d_in[5];
    const float* Wv  = (const float*)d_in[6];
    const float* bv  = (const float*)d_in[7];
    const float* Ws  = (const float*)d_in[8];
    const float* bs  = (const float*)d_in[9];
    float* out = (float*)d_out;

    float *qkvs, *hA, *hB;
    cudaGetSymbolAddress((void**)&qkvs, g_qkvs);
    cudaGetSymbolAddress((void**)&hA,   g_hA);
    cudaGetSymbolAddress((void**)&hB,   g_hB);

    // --- build CSR (dst -> list of src) once per launch ---
    zero_counts_kernel<<<(NN + 255) / 256, 256>>>();
    count_dst_kernel<<<(EE + 255) / 256, 256>>>(ei);
    exscan_kernel<<<1, 1024>>>();
    fill_csr_kernel<<<(EE + 255) / 256, 256>>>(ei);

    dim3 gemm_grid(8, (NN + BM - 1) / BM);   // 8 col variants x 391 row tiles
    int edge_blocks = (NN + 7) / 8;          // 8 warps per block

    const float* hin = x;
    for (int l = 0; l < LL; l++) {
        size_t wo = (size_t)l * DD * HC;
        gemm_qkvs_kernel<<<gemm_grid, 256>>>(
            hin,
            Wq + wo, Wk + wo, Wv + wo, Ws + wo,
            bq + l * HC, bk + l * HC, bv + l * HC, bs + l * HC,
            qkvs, NN);

        float* hout = (l == LL - 1) ? out : ((l == 0) ? hA : hB);
        edge_attn_kernel<<<edge_blocks, 256>>>(qkvs, hout);
        hin = hout;
    }
}